// round 7
// baseline (speedup 1.0000x reference)
#include <cuda_runtime.h>
#include <cuda_fp16.h>

// Trilinear interpolation, fp16 cell-table:
//   Pass 1 (repack): y (8,64^3 f32) -> g_tab (8,63^3 cells x 8 corners fp16,
//           16 B per cell). float4 row loads (4 rows x (float4 + 1 scalar)).
//   Pass 2 (interp): 8 points/thread, front-batched: 8 independent LDG.128
//           gathers in flight per thread, then fp32 lerp tree.

#define VOL    262144        // 64^3
#define MTOT   884736        // 96^3
#define NC1    63
#define NC3    250047        // 63^3
#define NCELLS (8 * NC3)     // 2,000,376
#define TPB_PTS 110592       // threads per batch in interp = MTOT/8

// 32 MB static scratch table: one uint4 (8 x fp16) per cell
__device__ uint4 g_tab[NCELLS];

__device__ __forceinline__ unsigned pack2(float a, float b) {
    __half2 h = __floats2half2_rn(a, b);
    return *reinterpret_cast<unsigned*>(&h);
}

// Each thread builds 4 (or 3 at the row tail) consecutive cells along z.
// 16 quads per 63-cell row; quad 15 covers cells 60..62.
__global__ void __launch_bounds__(256) repack_kernel(const float* __restrict__ y)
{
    int id = blockIdx.x * blockDim.x + threadIdx.x;
    const int TOTAL = 8 * 63 * 63 * 16;      // 508,032
    if (id >= TOTAL) return;

    int kq = id & 15;
    int r  = id >> 4;                         // (b*63+i)*63+j
    int j  = r % 63;
    int ij = r / 63;
    int i  = ij % 63;
    int b  = ij / 63;
    int k0 = kq * 4;

    const float* p0 = y + (size_t)b * VOL + i * 4096 + j * 64 + k0; // (i,   j  )
    const float* p1 = p0 + 64;                                      // (i,   j+1)
    const float* p2 = p0 + 4096;                                    // (i+1, j  )
    const float* p3 = p0 + 4160;                                    // (i+1, j+1)

    // k0 in {0,4,...,60} -> 16B-aligned float4 loads; element 4 separate.
    float4 q0 = __ldg(reinterpret_cast<const float4*>(p0));
    float4 q1 = __ldg(reinterpret_cast<const float4*>(p1));
    float4 q2 = __ldg(reinterpret_cast<const float4*>(p2));
    float4 q3 = __ldg(reinterpret_cast<const float4*>(p3));
    bool full = (k0 != 60);
    float e0 = full ? __ldg(p0 + 4) : 0.f;
    float e1 = full ? __ldg(p1 + 4) : 0.f;
    float e2 = full ? __ldg(p2 + 4) : 0.f;
    float e3 = full ? __ldg(p3 + 4) : 0.f;

    float a0[5] = {q0.x, q0.y, q0.z, q0.w, e0};
    float a1[5] = {q1.x, q1.y, q1.z, q1.w, e1};
    float a2[5] = {q2.x, q2.y, q2.z, q2.w, e2};
    float a3[5] = {q3.x, q3.y, q3.z, q3.w, e3};

    int ncell = full ? 4 : 3;
    size_t cbase = (((size_t)(b * 63 + i) * 63 + j) * 63) + k0;

#pragma unroll
    for (int c = 0; c < 4; c++) {
        if (c < ncell) {
            uint4 cell;
            cell.x = pack2(a0[c], a0[c + 1]);   // v000, v001
            cell.y = pack2(a1[c], a1[c + 1]);   // v010, v011
            cell.z = pack2(a2[c], a2[c + 1]);   // v100, v101
            cell.w = pack2(a3[c], a3[c + 1]);   // v110, v111
            g_tab[cbase + c] = cell;
        }
    }
}

__device__ __forceinline__ float lerp1(float a, float b, float t) {
    return fmaf(t, b - a, a);
}

__device__ __forceinline__ float2 h2f(unsigned u) {
    __half2 h = *reinterpret_cast<__half2*>(&u);
    return __half22float2(h);
}

__global__ void __launch_bounds__(256) trilerp_kernel(
    const float* __restrict__ xn,
    float* __restrict__ out)
{
    int t = blockIdx.x * 256 + threadIdx.x;   // grid sized exactly

    // 8 points = 24 floats = 6 float4
    const float4* xv = reinterpret_cast<const float4*>(xn) + (size_t)t * 6;
    float4 X[6];
#pragma unroll
    for (int i = 0; i < 6; i++) X[i] = __ldg(xv + i);
    const float* c = &X[0].x;

    int b = t / TPB_PTS;                       // batch (8 points never straddle)
    int base = b * NC3;

    // Phase 1: all indices + fractions
    int   cell[8];
    float f0[8], f1[8], f2[8];
#pragma unroll
    for (int p = 0; p < 8; p++) {
        float r0 = c[3 * p + 0] * 63.0f;
        float r1 = c[3 * p + 1] * 63.0f;
        float r2 = c[3 * p + 2] * 63.0f;
        int i0 = min((int)r0, 62);
        int i1 = min((int)r1, 62);
        int i2 = min((int)r2, 62);
        f0[p] = r0 - (float)i0;
        f1[p] = r1 - (float)i1;
        f2[p] = r2 - (float)i2;
        cell[p] = base + (i0 * NC1 + i1) * NC1 + i2;
    }

    // Phase 2: 8 independent gathers in flight
    uint4 q[8];
#pragma unroll
    for (int p = 0; p < 8; p++) q[p] = __ldg(g_tab + cell[p]);

    // Phase 3: lerp trees
    float r[8];
#pragma unroll
    for (int p = 0; p < 8; p++) {
        float2 e0 = h2f(q[p].x);   // v000, v001
        float2 e1 = h2f(q[p].y);   // v010, v011
        float2 e2 = h2f(q[p].z);   // v100, v101
        float2 e3 = h2f(q[p].w);   // v110, v111
        float v00 = lerp1(e0.x, e0.y, f2[p]);
        float v01 = lerp1(e1.x, e1.y, f2[p]);
        float v10 = lerp1(e2.x, e2.y, f2[p]);
        float v11 = lerp1(e3.x, e3.y, f2[p]);
        float v0  = lerp1(v00, v01, f1[p]);
        float v1  = lerp1(v10, v11, f1[p]);
        r[p]      = lerp1(v0, v1, f0[p]);
    }

    float4* o = reinterpret_cast<float4*>(out) + (size_t)t * 2;
    o[0] = make_float4(r[0], r[1], r[2], r[3]);
    o[1] = make_float4(r[4], r[5], r[6], r[7]);
}

extern "C" void kernel_launch(void* const* d_in, const int* in_sizes, int n_in,
                              void* d_out, int out_size)
{
    const float* y  = (const float*)d_in[0];   // (8, 64,64,64)
    const float* xn = (const float*)d_in[1];   // (8, 96^3, 3)
    float* out      = (float*)d_out;           // (8, 96^3)

    const int RTOTAL = 8 * 63 * 63 * 16;       // 508,032
    repack_kernel<<<(RTOTAL + 255) / 256, 256>>>(y);

    int total8 = out_size / 8;                 // 884,736 = 3456 * 256
    trilerp_kernel<<<total8 / 256, 256>>>(xn, out);
}

// round 9
// speedup vs baseline: 1.2176x; 1.2176x over previous
#include <cuda_runtime.h>
#include <cuda_fp16.h>

// Trilinear interpolation, fp16 cell-table:
//   Pass 1 (repack): y (8,64^3 f32) -> g_tab (8,63^3 cells x 8 fp16 corners,
//           16 B per cell).
//   Pass 2 (interp): 4 points/thread; the 4 cell gathers are issued via
//           asm volatile LDG.128 so ptxas CANNOT serialize them (R6 showed
//           it collapses C-level batching back to 32 regs / MLP=1).

#define VOL    262144        // 64^3
#define MTOT   884736        // 96^3
#define NC1    63
#define NC3    250047        // 63^3
#define NCELLS (8 * NC3)     // 2,000,376

// 32 MB static scratch table: one uint4 (8 x fp16) per cell
__device__ uint4 g_tab[NCELLS];

__device__ __forceinline__ unsigned pack2(float a, float b) {
    __half2 h = __floats2half2_rn(a, b);
    return *reinterpret_cast<unsigned*>(&h);
}

__global__ void __launch_bounds__(256) repack_kernel(const float* __restrict__ y)
{
    int id = blockIdx.x * blockDim.x + threadIdx.x;
    const int TOTAL = 8 * 63 * 63 * 16;      // 508,032
    if (id >= TOTAL) return;

    int kq = id & 15;
    int r  = id >> 4;                         // (b*63+i)*63+j
    int j  = r % 63;
    int ij = r / 63;
    int i  = ij % 63;
    int b  = ij / 63;
    int k0 = kq * 4;

    const float* p0 = y + (size_t)b * VOL + i * 4096 + j * 64 + k0; // (i,   j  )
    const float* p1 = p0 + 64;                                      // (i,   j+1)
    const float* p2 = p0 + 4096;                                    // (i+1, j  )
    const float* p3 = p0 + 4160;                                    // (i+1, j+1)

    float4 q0 = __ldg(reinterpret_cast<const float4*>(p0));
    float4 q1 = __ldg(reinterpret_cast<const float4*>(p1));
    float4 q2 = __ldg(reinterpret_cast<const float4*>(p2));
    float4 q3 = __ldg(reinterpret_cast<const float4*>(p3));
    bool full = (k0 != 60);
    float e0 = full ? __ldg(p0 + 4) : 0.f;
    float e1 = full ? __ldg(p1 + 4) : 0.f;
    float e2 = full ? __ldg(p2 + 4) : 0.f;
    float e3 = full ? __ldg(p3 + 4) : 0.f;

    float a0[5] = {q0.x, q0.y, q0.z, q0.w, e0};
    float a1[5] = {q1.x, q1.y, q1.z, q1.w, e1};
    float a2[5] = {q2.x, q2.y, q2.z, q2.w, e2};
    float a3[5] = {q3.x, q3.y, q3.z, q3.w, e3};

    int ncell = full ? 4 : 3;
    size_t cbase = (((size_t)(b * 63 + i) * 63 + j) * 63) + k0;

#pragma unroll
    for (int c = 0; c < 4; c++) {
        if (c < ncell) {
            uint4 cell;
            cell.x = pack2(a0[c], a0[c + 1]);
            cell.y = pack2(a1[c], a1[c + 1]);
            cell.z = pack2(a2[c], a2[c + 1]);
            cell.w = pack2(a3[c], a3[c + 1]);
            g_tab[cbase + c] = cell;
        }
    }
}

__device__ __forceinline__ float lerp1(float a, float b, float t) {
    return fmaf(t, b - a, a);
}

__device__ __forceinline__ float2 h2f(unsigned u) {
    __half2 h = *reinterpret_cast<__half2*>(&u);
    return __half22float2(h);
}

// Non-collapsible 16B gather: asm volatile pins issue order and live ranges.
__device__ __forceinline__ void ldg128_v(const uint4* p,
                                         unsigned& a, unsigned& b,
                                         unsigned& c, unsigned& d)
{
    asm volatile("ld.global.nc.v4.u32 {%0,%1,%2,%3}, [%4];"
                 : "=r"(a), "=r"(b), "=r"(c), "=r"(d)
                 : "l"(p));
}

__global__ void __launch_bounds__(256) trilerp_kernel(
    const float* __restrict__ xn,
    float* __restrict__ out,
    int total4)
{
    int t = blockIdx.x * 256 + threadIdx.x;
    if (t >= total4) return;

    const float4* xv = reinterpret_cast<const float4*>(xn) + (size_t)t * 3;
    float4 A = __ldg(xv + 0);
    float4 B = __ldg(xv + 1);
    float4 C = __ldg(xv + 2);
    float c[12] = {A.x, A.y, A.z, A.w,
                   B.x, B.y, B.z, B.w,
                   C.x, C.y, C.z, C.w};

    long long p0 = (long long)t * 4;
    int b = (int)(p0 / MTOT);
    int base = b * NC3;

    // Phase 1: indices + fractions for all 4 points
    int   cell[4];
    float f0[4], f1[4], f2[4];
#pragma unroll
    for (int p = 0; p < 4; p++) {
        float r0 = c[3 * p + 0] * 63.0f;
        float r1 = c[3 * p + 1] * 63.0f;
        float r2 = c[3 * p + 2] * 63.0f;
        int i0 = min((int)r0, 62);
        int i1 = min((int)r1, 62);
        int i2 = min((int)r2, 62);
        f0[p] = r0 - (float)i0;
        f1[p] = r1 - (float)i1;
        f2[p] = r2 - (float)i2;
        cell[p] = base + (i0 * NC1 + i1) * NC1 + i2;
    }

    // Phase 2: 4 gathers forced in flight (asm volatile, ordered)
    unsigned qa[4], qb[4], qc[4], qd[4];
#pragma unroll
    for (int p = 0; p < 4; p++)
        ldg128_v(g_tab + cell[p], qa[p], qb[p], qc[p], qd[p]);

    // Phase 3: lerp trees
    float4 res;
    float* rp = &res.x;
#pragma unroll
    for (int p = 0; p < 4; p++) {
        float2 e0 = h2f(qa[p]);   // v000, v001
        float2 e1 = h2f(qb[p]);   // v010, v011
        float2 e2 = h2f(qc[p]);   // v100, v101
        float2 e3 = h2f(qd[p]);   // v110, v111
        float v00 = lerp1(e0.x, e0.y, f2[p]);
        float v01 = lerp1(e1.x, e1.y, f2[p]);
        float v10 = lerp1(e2.x, e2.y, f2[p]);
        float v11 = lerp1(e3.x, e3.y, f2[p]);
        float v0  = lerp1(v00, v01, f1[p]);
        float v1  = lerp1(v10, v11, f1[p]);
        rp[p]     = lerp1(v0, v1, f0[p]);
    }

    reinterpret_cast<float4*>(out)[t] = res;
}

extern "C" void kernel_launch(void* const* d_in, const int* in_sizes, int n_in,
                              void* d_out, int out_size)
{
    const float* y  = (const float*)d_in[0];   // (8, 64,64,64)
    const float* xn = (const float*)d_in[1];   // (8, 96^3, 3)
    float* out      = (float*)d_out;           // (8, 96^3)

    const int RTOTAL = 8 * 63 * 63 * 16;       // 508,032
    repack_kernel<<<(RTOTAL + 255) / 256, 256>>>(y);

    int total4 = out_size / 4;                 // 1,769,472
    trilerp_kernel<<<(total4 + 255) / 256, 256>>>(xn, out, total4);
}

// round 10
// speedup vs baseline: 1.3698x; 1.1250x over previous
#include <cuda_runtime.h>
#include <cuda_fp16.h>

// Trilinear interpolation, fp16 cell-table + cp.async gathers:
//   Pass 1 (repack): y (8,64^3 f32) -> g_tab (8,63^3 cells x 8 fp16 corners,
//           16 B per cell).
//   Pass 2 (interp): 4 points/thread. Gathers issued as cp.async.cg 16B into
//           shared memory: no destination registers -> ptxas CANNOT collapse
//           the batch (R6/R8 showed reg-based batching gets serialized to
//           MLP=1). Guaranteed 4 gathers in flight per thread. Streaming
//           xnew/out use evict-first hints so the 32MB table stays in L2.

#define VOL    262144        // 64^3
#define MTOT   884736        // 96^3
#define NC1    63
#define NC3    250047        // 63^3
#define NCELLS (8 * NC3)     // 2,000,376

__device__ uint4 g_tab[NCELLS];

__device__ __forceinline__ unsigned pack2(float a, float b) {
    __half2 h = __floats2half2_rn(a, b);
    return *reinterpret_cast<unsigned*>(&h);
}

__global__ void __launch_bounds__(256) repack_kernel(const float* __restrict__ y)
{
    int id = blockIdx.x * blockDim.x + threadIdx.x;
    const int TOTAL = 8 * 63 * 63 * 16;      // 508,032
    if (id >= TOTAL) return;

    int kq = id & 15;
    int r  = id >> 4;                         // (b*63+i)*63+j
    int j  = r % 63;
    int ij = r / 63;
    int i  = ij % 63;
    int b  = ij / 63;
    int k0 = kq * 4;

    const float* p0 = y + (size_t)b * VOL + i * 4096 + j * 64 + k0;
    const float* p1 = p0 + 64;
    const float* p2 = p0 + 4096;
    const float* p3 = p0 + 4160;

    float4 q0 = __ldg(reinterpret_cast<const float4*>(p0));
    float4 q1 = __ldg(reinterpret_cast<const float4*>(p1));
    float4 q2 = __ldg(reinterpret_cast<const float4*>(p2));
    float4 q3 = __ldg(reinterpret_cast<const float4*>(p3));
    bool full = (k0 != 60);
    float e0 = full ? __ldg(p0 + 4) : 0.f;
    float e1 = full ? __ldg(p1 + 4) : 0.f;
    float e2 = full ? __ldg(p2 + 4) : 0.f;
    float e3 = full ? __ldg(p3 + 4) : 0.f;

    float a0[5] = {q0.x, q0.y, q0.z, q0.w, e0};
    float a1[5] = {q1.x, q1.y, q1.z, q1.w, e1};
    float a2[5] = {q2.x, q2.y, q2.z, q2.w, e2};
    float a3[5] = {q3.x, q3.y, q3.z, q3.w, e3};

    int ncell = full ? 4 : 3;
    size_t cbase = (((size_t)(b * 63 + i) * 63 + j) * 63) + k0;

#pragma unroll
    for (int c = 0; c < 4; c++) {
        if (c < ncell) {
            uint4 cell;
            cell.x = pack2(a0[c], a0[c + 1]);
            cell.y = pack2(a1[c], a1[c + 1]);
            cell.z = pack2(a2[c], a2[c + 1]);
            cell.w = pack2(a3[c], a3[c + 1]);
            g_tab[cbase + c] = cell;
        }
    }
}

__device__ __forceinline__ float lerp1(float a, float b, float t) {
    return fmaf(t, b - a, a);
}

__device__ __forceinline__ float2 h2f(unsigned u) {
    __half2 h = *reinterpret_cast<__half2*>(&u);
    return __half22float2(h);
}

__device__ __forceinline__ unsigned smem_u32(const void* p) {
    return (unsigned)__cvta_generic_to_shared(p);
}

__global__ void __launch_bounds__(256) trilerp_kernel(
    const float* __restrict__ xn,
    float* __restrict__ out,
    int total4)
{
    __shared__ uint4 stage[4 * 256];          // 16 KB: stage[p*256 + tid]

    int tid = threadIdx.x;
    int t = blockIdx.x * 256 + tid;
    if (t >= total4) return;

    // streaming reads: evict-first so the gather table keeps L2
    const float4* xv = reinterpret_cast<const float4*>(xn) + (size_t)t * 3;
    float4 A = __ldcs(xv + 0);
    float4 B = __ldcs(xv + 1);
    float4 C = __ldcs(xv + 2);
    float c[12] = {A.x, A.y, A.z, A.w,
                   B.x, B.y, B.z, B.w,
                   C.x, C.y, C.z, C.w};

    long long p0 = (long long)t * 4;
    int b = (int)(p0 / MTOT);
    int base = b * NC3;

    // Phase 1: indices + fractions, fire cp.async gather per point immediately
    float f0[4], f1[4], f2[4];
#pragma unroll
    for (int p = 0; p < 4; p++) {
        float r0 = c[3 * p + 0] * 63.0f;
        float r1 = c[3 * p + 1] * 63.0f;
        float r2 = c[3 * p + 2] * 63.0f;
        int i0 = min((int)r0, 62);
        int i1 = min((int)r1, 62);
        int i2 = min((int)r2, 62);
        f0[p] = r0 - (float)i0;
        f1[p] = r1 - (float)i1;
        f2[p] = r2 - (float)i2;
        int cell = base + (i0 * NC1 + i1) * NC1 + i2;
        unsigned saddr = smem_u32(&stage[p * 256 + tid]);
        const uint4* gptr = g_tab + cell;
        asm volatile("cp.async.cg.shared.global [%0], [%1], 16;"
                     :: "r"(saddr), "l"(gptr) : "memory");
    }
    asm volatile("cp.async.commit_group;");
    asm volatile("cp.async.wait_group 0;" ::: "memory");

    // Phase 2: read own cells from smem (conflict-free: lanes consecutive 16B)
    float4 res;
    float* rp = &res.x;
#pragma unroll
    for (int p = 0; p < 4; p++) {
        uint4 q = stage[p * 256 + tid];
        float2 e0 = h2f(q.x);   // v000, v001
        float2 e1 = h2f(q.y);   // v010, v011
        float2 e2 = h2f(q.z);   // v100, v101
        float2 e3 = h2f(q.w);   // v110, v111
        float v00 = lerp1(e0.x, e0.y, f2[p]);
        float v01 = lerp1(e1.x, e1.y, f2[p]);
        float v10 = lerp1(e2.x, e2.y, f2[p]);
        float v11 = lerp1(e3.x, e3.y, f2[p]);
        float v0  = lerp1(v00, v01, f1[p]);
        float v1  = lerp1(v10, v11, f1[p]);
        rp[p]     = lerp1(v0, v1, f0[p]);
    }

    __stcs(reinterpret_cast<float4*>(out) + t, res);
}

extern "C" void kernel_launch(void* const* d_in, const int* in_sizes, int n_in,
                              void* d_out, int out_size)
{
    const float* y  = (const float*)d_in[0];   // (8, 64,64,64)
    const float* xn = (const float*)d_in[1];   // (8, 96^3, 3)
    float* out      = (float*)d_out;           // (8, 96^3)

    const int RTOTAL = 8 * 63 * 63 * 16;       // 508,032
    repack_kernel<<<(RTOTAL + 255) / 256, 256>>>(y);

    int total4 = out_size / 4;                 // 1,769,472
    trilerp_kernel<<<(total4 + 255) / 256, 256>>>(xn, out, total4);
}